// round 15
// baseline (speedup 1.0000x reference)
#include <cuda_runtime.h>
#include <cstdint>

// CausalAttention via mma.sync int8 2-slice Ozaki quantization (3-IMMA fp32 emu).
// R15: HMMA shown rate-bound (rt=16, count = runtime). IMMA m16n8k32 packs 2x
// MACs/instr; 2+2-slice int8 with shared lo-accumulator = 3 IMMA per K=32 vs
// 4 HMMA per K=32 in R14, and ~16-bit effective precision per side (> fp16 11).
//   v ~= s_row * (q0 + q1/254),  C = sA*sB*( sum q0a*q0b + (q0a*q1b + q1a*q0b)/254 )

typedef unsigned int u32;

#define TPB 256
#define BK 64                  // K-chunk in int8 elems
#define LDB 80                 // padded smem row bytes (64 int8 + 16 pad; stride 20 banks)
#define TILE_B (128 * LDB)     // 10240 B per 128x64 int8 tile
#define OFF_A0 0
#define OFF_A1 TILE_B
#define OFF_B0 (2 * TILE_B)
#define OFF_B1 (3 * TILE_B)
#define BUF_B (4 * TILE_B)     // 40960
#define GEMM_SMEM (2 * BUF_B)  // 81920

// ---------------- scratch (no allocation anywhere) ----------------
__device__ int8_t g_X0[8192 * 1024], g_X1[8192 * 1024];
__device__ float  g_sX[8192];
__device__ float  g_WT[3 * 1024 * 1024];
__device__ int8_t g_W0[3 * 1024 * 1024], g_W1[3 * 1024 * 1024];
__device__ float  g_sW[3 * 1024];
__device__ float  g_Q[4 * 2048 * 1024];
__device__ float  g_K[4 * 2048 * 1024];
__device__ float  g_V[4 * 2048 * 1024];
__device__ int8_t g_Q0[4 * 2048 * 1024], g_Q1[4 * 2048 * 1024];
__device__ int8_t g_K0[4 * 2048 * 1024], g_K1[4 * 2048 * 1024];
__device__ float  g_sQ[8192], g_sK[8192];
__device__ float  g_VT[(size_t)4 * 1024 * 2048];
__device__ int8_t g_VT0[(size_t)4 * 1024 * 2048], g_VT1[(size_t)4 * 1024 * 2048];
__device__ float  g_sVT[4096];
__device__ float  g_S[(size_t)4 * 2048 * 2048];
__device__ int8_t g_P0[(size_t)4 * 2048 * 2048], g_P1[(size_t)4 * 2048 * 2048];
__device__ float  g_sP[8192];

// ---------------- helpers ----------------
__device__ __forceinline__ u32 smem_u32(const void* p) {
    u32 a;
    asm("{ .reg .u64 t; cvta.to.shared.u64 t, %1; cvt.u32.u64 %0, t; }"
        : "=r"(a) : "l"(p));
    return a;
}

__device__ __forceinline__ void cp_async16(u32 dst, const void* src) {
    asm volatile("cp.async.cg.shared.global [%0], [%1], 16;"
                 :: "r"(dst), "l"(src) : "memory");
}
#define CP_COMMIT() asm volatile("cp.async.commit_group;" ::: "memory")
#define CP_WAIT(N)  asm volatile("cp.async.wait_group %0;" :: "n"(N) : "memory")

__device__ __forceinline__ void ldmx4(u32 a, u32& r0, u32& r1, u32& r2, u32& r3) {
    asm volatile("ldmatrix.sync.aligned.m8n8.x4.shared.b16 {%0,%1,%2,%3}, [%4];"
                 : "=r"(r0), "=r"(r1), "=r"(r2), "=r"(r3) : "r"(a));
}

__device__ __forceinline__ void mma_s8(int c[4], const u32 a[4], const u32 b[2]) {
    asm volatile(
        "mma.sync.aligned.m16n8k32.row.col.s32.s8.s8.s32 "
        "{%0,%1,%2,%3}, {%4,%5,%6,%7}, {%8,%9}, {%0,%1,%2,%3};"
        : "+r"(c[0]), "+r"(c[1]), "+r"(c[2]), "+r"(c[3])
        : "r"(a[0]), "r"(a[1]), "r"(a[2]), "r"(a[3]), "r"(b[0]), "r"(b[1]));
}

// ---------------- GEMM core ----------------
// C[128x128 tile at (m0,n0)] = scale*sA[m]*sB[n]*(hi + lo/254), K-major int8.
__device__ __forceinline__ void gemm_core(
    const int8_t* __restrict__ A0, const int8_t* __restrict__ A1,
    const float* __restrict__ sA, int lda,
    const int8_t* __restrict__ B0, const int8_t* __restrict__ B1,
    const float* __restrict__ sB, int ldb,
    int m0, int n0, int Klen, float scale, float* __restrict__ Cf, int ldc)
{
    extern __shared__ char smem[];
    const u32 sbase = smem_u32(smem);
    const int tid = threadIdx.x;
    const int wid = tid >> 5;
    const int lane = tid & 31;
    const int warp_m = (wid & 3) * 32;   // 4 warps over M
    const int warp_n = (wid >> 2) * 64;  // 2 warps over N

    // cp.async mapping: each thread loads 2x16B per matrix tile.
    const int lrow = tid & 127;
    const int c0 = (tid >> 7) * 16;      // int8 col 0 or 16 (second seg at +32)
    const u32 dst = (u32)(lrow * LDB + c0);
    const int8_t* pA0 = A0 + (size_t)(m0 + lrow) * lda + c0;
    const int8_t* pA1 = A1 + (size_t)(m0 + lrow) * lda + c0;
    const int8_t* pB0 = B0 + (size_t)(n0 + lrow) * ldb + c0;
    const int8_t* pB1 = B1 + (size_t)(n0 + lrow) * ldb + c0;

    const int nch = Klen / BK;

    // ldmatrix base offsets (bytes, within a tile): row*(LDB) + (lane>>4)*16B
    const u32 lm_a = (u32)((warp_m + (lane & 15)) * LDB + (lane >> 4) * 16);
    const u32 lm_b = (u32)((warp_n + (lane & 15)) * LDB + (lane >> 4) * 16);

    int hi[2][8][4], lo[2][8][4];
#pragma unroll
    for (int i = 0; i < 2; ++i)
#pragma unroll
        for (int j = 0; j < 8; ++j)
#pragma unroll
            for (int q = 0; q < 4; ++q) { hi[i][j][q] = 0; lo[i][j][q] = 0; }

    // ---- prologue: load chunk 0 ----
    {
        const u32 ba = sbase;
        cp_async16(ba + OFF_A0 + dst,      pA0);
        cp_async16(ba + OFF_A0 + dst + 32, pA0 + 32);
        cp_async16(ba + OFF_A1 + dst,      pA1);
        cp_async16(ba + OFF_A1 + dst + 32, pA1 + 32);
        cp_async16(ba + OFF_B0 + dst,      pB0);
        cp_async16(ba + OFF_B0 + dst + 32, pB0 + 32);
        cp_async16(ba + OFF_B1 + dst,      pB1);
        cp_async16(ba + OFF_B1 + dst + 32, pB1 + 32);
        CP_COMMIT();
    }

    for (int c = 0; c < nch; ++c) {
        if (c + 1 < nch) {
            const u32 ba = sbase + ((c + 1) & 1) * BUF_B;
            const int k0 = (c + 1) * BK;
            cp_async16(ba + OFF_A0 + dst,      pA0 + k0);
            cp_async16(ba + OFF_A0 + dst + 32, pA0 + k0 + 32);
            cp_async16(ba + OFF_A1 + dst,      pA1 + k0);
            cp_async16(ba + OFF_A1 + dst + 32, pA1 + k0 + 32);
            cp_async16(ba + OFF_B0 + dst,      pB0 + k0);
            cp_async16(ba + OFF_B0 + dst + 32, pB0 + k0 + 32);
            cp_async16(ba + OFF_B1 + dst,      pB1 + k0);
            cp_async16(ba + OFF_B1 + dst + 32, pB1 + k0 + 32);
            CP_COMMIT();
            CP_WAIT(1);
        } else {
            CP_WAIT(0);
        }
        __syncthreads();

        const u32 ba = sbase + (c & 1) * BUF_B;
        const u32 aA0 = ba + OFF_A0 + lm_a;
        const u32 aA1 = ba + OFF_A1 + lm_a;
        const u32 aB0 = ba + OFF_B0 + lm_b;
        const u32 aB1 = ba + OFF_B1 + lm_b;

#pragma unroll
        for (int ks = 0; ks < BK / 32; ++ks) {     // 2 k32-steps per chunk
            const u32 ko = (u32)(ks * 32);         // 32 bytes = k32
            u32 b0[8][2], b1[8][2];
#pragma unroll
            for (int g = 0; g < 4; ++g) {          // 16 n-rows per ldmatrix.x4
                u32 r0, r1, r2, r3;
                ldmx4(aB0 + ko + (u32)(g * 16 * LDB), r0, r1, r2, r3);
                b0[2 * g][0] = r0; b0[2 * g][1] = r2;
                b0[2 * g + 1][0] = r1; b0[2 * g + 1][1] = r3;
                ldmx4(aB1 + ko + (u32)(g * 16 * LDB), r0, r1, r2, r3);
                b1[2 * g][0] = r0; b1[2 * g][1] = r2;
                b1[2 * g + 1][0] = r1; b1[2 * g + 1][1] = r3;
            }
#pragma unroll
            for (int mf = 0; mf < 2; ++mf) {
                u32 a0[4], a1[4];
                ldmx4(aA0 + ko + (u32)(mf * 16 * LDB), a0[0], a0[1], a0[2], a0[3]);
                ldmx4(aA1 + ko + (u32)(mf * 16 * LDB), a1[0], a1[1], a1[2], a1[3]);
#pragma unroll
                for (int nf = 0; nf < 8; ++nf) {
                    mma_s8(hi[mf][nf], a0, b0[nf]);   // q0a*q0b
                    mma_s8(lo[mf][nf], a0, b1[nf]);   // q0a*q1b
                    mma_s8(lo[mf][nf], a1, b0[nf]);   // q1a*q0b (shared acc)
                }
            }
        }
        __syncthreads();
    }

    // ---- epilogue: dequantize ----
    const int erow = lane >> 2;
    const int ecol = (lane & 3) * 2;
    const float r254 = 1.0f / 254.0f;
#pragma unroll
    for (int mf = 0; mf < 2; ++mf) {
        const int r0i = m0 + warp_m + mf * 16 + erow;
        const float sa0 = sA[r0i] * scale;
        const float sa1 = sA[r0i + 8] * scale;
#pragma unroll
        for (int nf = 0; nf < 8; ++nf) {
            const int cc = n0 + warp_n + nf * 8 + ecol;
            const float sb0 = sB[cc], sb1 = sB[cc + 1];
            float v0 = ((float)hi[mf][nf][0] + (float)lo[mf][nf][0] * r254) * sa0 * sb0;
            float v1 = ((float)hi[mf][nf][1] + (float)lo[mf][nf][1] * r254) * sa0 * sb1;
            float v2 = ((float)hi[mf][nf][2] + (float)lo[mf][nf][2] * r254) * sa1 * sb0;
            float v3 = ((float)hi[mf][nf][3] + (float)lo[mf][nf][3] * r254) * sa1 * sb1;
            float2 w0 = {v0, v1}, w1 = {v2, v3};
            *(float2*)(Cf + (size_t)r0i * ldc + cc) = w0;
            *(float2*)(Cf + (size_t)(r0i + 8) * ldc + cc) = w1;
        }
    }
}

// ---------------- row quantization (2-slice int8) ----------------
__device__ __forceinline__ void rowquant_body(
    const float* __restrict__ src, int8_t* __restrict__ q0, int8_t* __restrict__ q1,
    float* __restrict__ s, int cols)
{
    const size_t base = (size_t)blockIdx.x * cols;
    const int tid = threadIdx.x;
    __shared__ float red[TPB];
    float m = 0.0f;
    for (int i = tid; i < cols; i += TPB) m = fmaxf(m, fabsf(src[base + i]));
    red[tid] = m;
    __syncthreads();
#pragma unroll
    for (int st = TPB / 2; st > 0; st >>= 1) {
        if (tid < st) red[tid] = fmaxf(red[tid], red[tid + st]);
        __syncthreads();
    }
    const float mx = red[0];
    const float sv = (mx > 0.0f) ? mx * (1.0f / 127.0f) : 1.0f;
    const float inv = 1.0f / sv;
    if (tid == 0) s[blockIdx.x] = sv;
    for (int i = tid; i < cols; i += TPB) {
        float v = src[base + i];
        float h = rintf(v * inv);
        h = fminf(fmaxf(h, -127.0f), 127.0f);
        float l = rintf((v - h * sv) * inv * 254.0f);
        l = fminf(fmaxf(l, -127.0f), 127.0f);
        q0[base + i] = (int8_t)(int)h;
        q1[base + i] = (int8_t)(int)l;
    }
}

__global__ void quant_x_kernel(const float* __restrict__ x) {
    rowquant_body(x, g_X0, g_X1, g_sX, 1024);
}
__global__ void quant_w_kernel() { rowquant_body(g_WT, g_W0, g_W1, g_sW, 1024); }
__global__ void quant_q_kernel() { rowquant_body(g_Q, g_Q0, g_Q1, g_sQ, 1024); }
__global__ void quant_k_kernel() { rowquant_body(g_K, g_K0, g_K1, g_sK, 1024); }
__global__ void quant_vt_kernel() { rowquant_body(g_VT, g_VT0, g_VT1, g_sVT, 2048); }

// ---------------- transpose kernels (fp32) ----------------
__global__ void wt_kernel(const float* __restrict__ Wq, const float* __restrict__ Wk,
                          const float* __restrict__ Wv) {
    __shared__ float t[32][33];
    const float* W = (blockIdx.z == 0) ? Wq : (blockIdx.z == 1) ? Wk : Wv;
    float* T = g_WT + (size_t)blockIdx.z * 1024 * 1024;
    const int n0 = blockIdx.x * 32, k0 = blockIdx.y * 32;
    const int tx = threadIdx.x, ty = threadIdx.y;
#pragma unroll
    for (int i = 0; i < 4; ++i)
        t[ty + i * 8][tx] = W[(size_t)(k0 + ty + i * 8) * 1024 + n0 + tx];
    __syncthreads();
#pragma unroll
    for (int i = 0; i < 4; ++i)
        T[(size_t)(n0 + ty + i * 8) * 1024 + k0 + tx] = t[tx][ty + i * 8];
}

__global__ void vt_kernel() {
    __shared__ float t[32][33];
    const int b = blockIdx.z;
    const float* V = g_V + (size_t)b * 2048 * 1024;
    float* T = g_VT + (size_t)b * 1024 * 2048;
    const int e0 = blockIdx.x * 32, k0 = blockIdx.y * 32;
    const int tx = threadIdx.x, ty = threadIdx.y;
#pragma unroll
    for (int i = 0; i < 4; ++i)
        t[ty + i * 8][tx] = V[(size_t)(k0 + ty + i * 8) * 1024 + e0 + tx];
    __syncthreads();
#pragma unroll
    for (int i = 0; i < 4; ++i)
        T[(size_t)(e0 + ty + i * 8) * 2048 + k0 + tx] = t[tx][ty + i * 8];
}

// ---------------- GEMM kernels ----------------
__global__ void __launch_bounds__(TPB, 1)
proj_kernel() {
    const int z = blockIdx.z;
    const int m0 = blockIdx.y * 128;
    const int n0 = blockIdx.x * 128;
    const int8_t* B0 = g_W0 + (size_t)z * 1024 * 1024;
    const int8_t* B1 = g_W1 + (size_t)z * 1024 * 1024;
    const float* sB = g_sW + (size_t)z * 1024;
    float* C = (z == 0) ? g_Q : (z == 1) ? g_K : g_V;
    gemm_core(g_X0, g_X1, g_sX, 1024, B0, B1, sB, 1024,
              m0, n0, 1024, 1.0f, C, 1024);
}

__global__ void __launch_bounds__(TPB, 1)
score_kernel() {
    const int kb = blockIdx.x, qb = blockIdx.y, b = blockIdx.z;
    if (kb > qb) return;
    const size_t o = (size_t)b * 2048 * 1024;
    gemm_core(g_Q0 + o, g_Q1 + o, g_sQ + b * 2048, 1024,
              g_K0 + o, g_K1 + o, g_sK + b * 2048, 1024,
              qb * 128, kb * 128, 1024, 0.03125f,
              g_S + (size_t)b * 2048 * 2048, 2048);
}

__global__ void __launch_bounds__(TPB, 1)
pv_kernel(float* __restrict__ out) {
    const int nb = blockIdx.x, qb = blockIdx.y, b = blockIdx.z;
    const size_t po = (size_t)b * 2048 * 2048;
    const size_t vo = (size_t)b * 1024 * 2048;
    gemm_core(g_P0 + po, g_P1 + po, g_sP + b * 2048, 2048,
              g_VT0 + vo, g_VT1 + vo, g_sVT + b * 1024, 2048,
              qb * 128, nb * 128, (qb + 1) * 128, 1.0f,
              out + (size_t)b * 2048 * 1024, 1024);
}

// ---------------- softmax (fp32 in, int8 2-slice out) ----------------
__global__ void softmax_kernel() {
    const int q = blockIdx.x, b = blockIdx.y;
    float* row = g_S + ((size_t)b * 2048 + q) * 2048;
    int8_t* p0 = g_P0 + ((size_t)b * 2048 + q) * 2048;
    int8_t* p1 = g_P1 + ((size_t)b * 2048 + q) * 2048;
    const int len = q + 1;
    const int tid = threadIdx.x;
    __shared__ float red[TPB];

    float m = -1e30f;
    for (int i = tid; i < len; i += TPB) m = fmaxf(m, row[i]);
    red[tid] = m;
    __syncthreads();
#pragma unroll
    for (int s = TPB / 2; s > 0; s >>= 1) {
        if (tid < s) red[tid] = fmaxf(red[tid], red[tid + s]);
        __syncthreads();
    }
    m = red[0];
    __syncthreads();

    float sum = 0.0f;
    for (int i = tid; i < len; i += TPB) {
        float e = __expf(row[i] - m);
        row[i] = e;
        sum += e;
    }
    red[tid] = sum;
    __syncthreads();
#pragma unroll
    for (int s = TPB / 2; s > 0; s >>= 1) {
        if (tid < s) red[tid] += red[tid + s];
        __syncthreads();
    }
    const float inv = 1.0f / red[0];   // max e = exp(0) = 1, so max p = inv
    __syncthreads();

    // quantize: p = e*inv ~= sP*(q0 + q1/254) with sP = inv/127
    if (tid == 0) g_sP[b * 2048 + q] = inv * (1.0f / 127.0f);
    for (int i = tid; i < len; i += TPB) {
        float e = row[i];                       // in [0, 1]
        float h = rintf(e * 127.0f);            // [0, 127]
        float l = rintf((e * 127.0f - h) * 254.0f);
        l = fminf(fmaxf(l, -127.0f), 127.0f);
        p0[i] = (int8_t)(int)h;
        p1[i] = (int8_t)(int)l;
    }
    const int klim = ((q >> 7) + 1) << 7;  // zero up to 128-tile boundary
    for (int i = len + tid; i < klim; i += TPB) { p0[i] = 0; p1[i] = 0; }
}

// ---------------- launch ----------------
extern "C" void kernel_launch(void* const* d_in, const int* in_sizes, int n_in,
                              void* d_out, int out_size) {
    const float* x  = (const float*)d_in[0];
    const float* Wq = (const float*)d_in[1];
    const float* Wk = (const float*)d_in[2];
    const float* Wv = (const float*)d_in[3];
    float* out = (float*)d_out;

    cudaFuncSetAttribute(proj_kernel,  cudaFuncAttributeMaxDynamicSharedMemorySize, GEMM_SMEM);
    cudaFuncSetAttribute(score_kernel, cudaFuncAttributeMaxDynamicSharedMemorySize, GEMM_SMEM);
    cudaFuncSetAttribute(pv_kernel,    cudaFuncAttributeMaxDynamicSharedMemorySize, GEMM_SMEM);

    quant_x_kernel<<<8192, TPB>>>(x);
    wt_kernel<<<dim3(32, 32, 3), dim3(32, 8)>>>(Wq, Wk, Wv);
    quant_w_kernel<<<3072, TPB>>>();
    proj_kernel<<<dim3(8, 64, 3), TPB, GEMM_SMEM>>>();
    quant_q_kernel<<<8192, TPB>>>();
    quant_k_kernel<<<8192, TPB>>>();
    vt_kernel<<<dim3(32, 64, 4), dim3(32, 8)>>>();
    quant_vt_kernel<<<4096, TPB>>>();
    score_kernel<<<dim3(16, 16, 4), TPB, GEMM_SMEM>>>();
    softmax_kernel<<<dim3(2048, 4), TPB>>>();
    pv_kernel<<<dim3(8, 16, 4), TPB, GEMM_SMEM>>>(out);
}

// round 16
// speedup vs baseline: 6.2573x; 6.2573x over previous
#include <cuda_runtime.h>
#include <cuda_fp16.h>
#include <cstdint>

// CausalAttention via pure-fp16 mma.sync (1 HMMA per k16-step).
// R16: rate model locked in across R10-R15: fallback HMMA = 128 MACs/cyc/SMSP,
// runtime == MMA-term count. IMMA fallback is 5x slower (R15) - dead end.
// So: single-term fp16 GEMMs everywhere (43G MMA-MACs ~= 300us GEMM floor).
// Precision anchor: R14 (A-side-only fp16) = 4.15e-4; symmetric B-side adds
// in quadrature -> predicted ~6e-4 < 1e-3 gate.

typedef unsigned int u32;

#define TPB 256
#define BK 64                 // K-chunk in fp16 elems
#define LDSS 72               // padded smem row (144B) - conflict-free ldmatrix
#define TILE_B (128 * LDSS * 2)          // 18432 B per 128x64 fp16 tile
#define OFF_A 0
#define OFF_B TILE_B
#define BUF_B (2 * TILE_B)               // A, B = 36864
#define GEMM_SMEM (2 * BUF_B)            // double buffer = 73728 B

// ---------------- scratch (no allocation anywhere) ----------------
__device__ __half g_xh[8192 * 1024];
__device__ __half g_WTh[3 * 1024 * 1024];
__device__ __half g_Qh[4 * 2048 * 1024];
__device__ __half g_Kh[4 * 2048 * 1024];
__device__ float  g_V[4 * 2048 * 1024];
__device__ __half g_VTh[(size_t)4 * 1024 * 2048];
__device__ float  g_S[(size_t)4 * 2048 * 2048];
__device__ __half g_Ph[(size_t)4 * 2048 * 2048];

// ---------------- helpers ----------------
__device__ __forceinline__ u32 smem_u32(const void* p) {
    u32 a;
    asm("{ .reg .u64 t; cvta.to.shared.u64 t, %1; cvt.u32.u64 %0, t; }"
        : "=r"(a) : "l"(p));
    return a;
}

__device__ __forceinline__ void cp_async16(u32 dst, const void* src) {
    asm volatile("cp.async.cg.shared.global [%0], [%1], 16;"
                 :: "r"(dst), "l"(src) : "memory");
}
#define CP_COMMIT() asm volatile("cp.async.commit_group;" ::: "memory")
#define CP_WAIT(N)  asm volatile("cp.async.wait_group %0;" :: "n"(N) : "memory")

__device__ __forceinline__ void ldmx4(u32 a, u32& r0, u32& r1, u32& r2, u32& r3) {
    asm volatile("ldmatrix.sync.aligned.m8n8.x4.shared.b16 {%0,%1,%2,%3}, [%4];"
                 : "=r"(r0), "=r"(r1), "=r"(r2), "=r"(r3) : "r"(a));
}

__device__ __forceinline__ void mma_f32(float c[4], const u32 a[4], const u32 b[2]) {
    asm volatile(
        "mma.sync.aligned.m16n8k16.row.col.f32.f16.f16.f32 "
        "{%0,%1,%2,%3}, {%4,%5,%6,%7}, {%8,%9}, {%0,%1,%2,%3};"
        : "+f"(c[0]), "+f"(c[1]), "+f"(c[2]), "+f"(c[3])
        : "r"(a[0]), "r"(a[1]), "r"(a[2]), "r"(a[3]), "r"(b[0]), "r"(b[1]));
}

// ---------------- GEMM core ----------------
// C[128x128 tile at (m0,n0)] = sum_k A[m,k]*B[n,k]; A,B fp16 K-major.
// MODE 0: fp32 out (Cf)*scale.   MODE 2: fp16 out (Ch).
template <int MODE>
__device__ __forceinline__ void gemm_core(
    const __half* __restrict__ A, int lda,
    const __half* __restrict__ B, int ldb,
    int m0, int n0, int Klen, float scale,
    float* __restrict__ Cf, __half* __restrict__ Ch, int ldc)
{
    extern __shared__ char smem[];
    const u32 sbase = smem_u32(smem);
    const int tid = threadIdx.x;
    const int wid = tid >> 5;
    const int lane = tid & 31;
    const int warp_m = (wid & 3) * 32;   // 4 warps over M
    const int warp_n = (wid >> 2) * 64;  // 2 warps over N

    // cp.async mapping: 32 rows x 8 segs(16B) per pass, 4 passes per tile
    const int lrow = tid >> 3;            // 0..31
    const int lseg = (tid & 7) * 8;       // elem col 0..56
    const u32 dst_off = (u32)(lrow * LDSS + lseg) * 2;
    const __half* pA = A + (size_t)(m0 + lrow) * lda + lseg;
    const __half* pB = B + (size_t)(n0 + lrow) * ldb + lseg;

    const int nch = Klen / BK;

    // ldmatrix base offsets (within a tile)
    const u32 lm_a0 = (u32)((warp_m + (lane & 15)) * LDSS + (lane >> 4) * 8) * 2;
    const u32 lm_b0 = (u32)((warp_n + (lane & 15)) * LDSS + (lane >> 4) * 8) * 2;

    float acc[2][8][4];
#pragma unroll
    for (int i = 0; i < 2; ++i)
#pragma unroll
        for (int j = 0; j < 8; ++j)
#pragma unroll
            for (int q = 0; q < 4; ++q) acc[i][j][q] = 0.0f;

    // ---- prologue: load chunk 0 ----
    {
        const u32 ba = sbase;
#pragma unroll
        for (int p = 0; p < 4; ++p) {
            const u32 d = ba + dst_off + (u32)(32 * p * LDSS) * 2;
            cp_async16(d + OFF_A, pA + (size_t)(32 * p) * lda);
            cp_async16(d + OFF_B, pB + (size_t)(32 * p) * ldb);
        }
        CP_COMMIT();
    }

    for (int c = 0; c < nch; ++c) {
        // issue loads for chunk c+1 into the other buffer
        if (c + 1 < nch) {
            const u32 ba = sbase + ((c + 1) & 1) * BUF_B;
            const int k0 = (c + 1) * BK;
#pragma unroll
            for (int p = 0; p < 4; ++p) {
                const u32 d = ba + dst_off + (u32)(32 * p * LDSS) * 2;
                cp_async16(d + OFF_A, pA + (size_t)(32 * p) * lda + k0);
                cp_async16(d + OFF_B, pB + (size_t)(32 * p) * ldb + k0);
            }
            CP_COMMIT();
            CP_WAIT(1);   // chunk c complete, c+1 in flight
        } else {
            CP_WAIT(0);
        }
        __syncthreads();

        const u32 ba = sbase + (c & 1) * BUF_B;
        const u32 aA = ba + OFF_A + lm_a0;
        const u32 aB = ba + OFF_B + lm_b0;

#pragma unroll
        for (int ks = 0; ks < BK / 16; ++ks) {
            const u32 ko = (u32)(ks * 16) * 2;
            u32 bb[8][2];
#pragma unroll
            for (int g = 0; g < 4; ++g) {   // 16 n-rows per ldmatrix.x4
                u32 r0, r1, r2, r3;
                ldmx4(aB + ko + (u32)(g * 16 * LDSS) * 2, r0, r1, r2, r3);
                bb[2 * g][0] = r0; bb[2 * g][1] = r2;
                bb[2 * g + 1][0] = r1; bb[2 * g + 1][1] = r3;
            }
#pragma unroll
            for (int mf = 0; mf < 2; ++mf) {
                u32 ah[4];
                ldmx4(aA + ko + (u32)(mf * 16 * LDSS) * 2,
                      ah[0], ah[1], ah[2], ah[3]);
#pragma unroll
                for (int nf = 0; nf < 8; ++nf)
                    mma_f32(acc[mf][nf], ah, bb[nf]);
            }
        }
        __syncthreads();
    }

    // ---- epilogue ----
    const int erow = lane >> 2;
    const int ecol = (lane & 3) * 2;
#pragma unroll
    for (int mf = 0; mf < 2; ++mf) {
        const int rbase = m0 + warp_m + mf * 16 + erow;
#pragma unroll
        for (int nf = 0; nf < 8; ++nf) {
            const int ccol = n0 + warp_n + nf * 8 + ecol;
            const float v0 = acc[mf][nf][0], v1 = acc[mf][nf][1];
            const float v2 = acc[mf][nf][2], v3 = acc[mf][nf][3];
            if (MODE == 0) {
                float2 w0, w1;
                w0.x = v0 * scale; w0.y = v1 * scale;
                w1.x = v2 * scale; w1.y = v3 * scale;
                *(float2*)(Cf + (size_t)rbase * ldc + ccol) = w0;
                *(float2*)(Cf + (size_t)(rbase + 8) * ldc + ccol) = w1;
            } else {
                *(__half2*)(Ch + (size_t)rbase * ldc + ccol) =
                    __halves2half2(__float2half_rn(v0), __float2half_rn(v1));
                *(__half2*)(Ch + (size_t)(rbase + 8) * ldc + ccol) =
                    __halves2half2(__float2half_rn(v2), __float2half_rn(v3));
            }
        }
    }
}

// ---------------- prep kernels ----------------
__global__ void split_x_kernel(const float* __restrict__ x) {
    const int n = 8192 * 1024;
    for (int i = blockIdx.x * blockDim.x + threadIdx.x; i < n; i += gridDim.x * blockDim.x)
        g_xh[i] = __float2half_rn(x[i]);
}

__global__ void wt_kernel(const float* __restrict__ Wq, const float* __restrict__ Wk,
                          const float* __restrict__ Wv) {
    __shared__ float t[32][33];
    const float* W = (blockIdx.z == 0) ? Wq : (blockIdx.z == 1) ? Wk : Wv;
    __half* Th = g_WTh + (size_t)blockIdx.z * 1024 * 1024;
    const int n0 = blockIdx.x * 32, k0 = blockIdx.y * 32;
    const int tx = threadIdx.x, ty = threadIdx.y;
#pragma unroll
    for (int i = 0; i < 4; ++i)
        t[ty + i * 8][tx] = W[(size_t)(k0 + ty + i * 8) * 1024 + n0 + tx];
    __syncthreads();
#pragma unroll
    for (int i = 0; i < 4; ++i)
        Th[(size_t)(n0 + ty + i * 8) * 1024 + k0 + tx] =
            __float2half_rn(t[tx][ty + i * 8]);   // = W[k0+tx][n0+ty+i*8]
}

__global__ void vt_kernel() {
    __shared__ float t[32][33];
    const int b = blockIdx.z;
    const float* V = g_V + (size_t)b * 2048 * 1024;
    __half* Th = g_VTh + (size_t)b * 1024 * 2048;
    const int e0 = blockIdx.x * 32, k0 = blockIdx.y * 32;
    const int tx = threadIdx.x, ty = threadIdx.y;
#pragma unroll
    for (int i = 0; i < 4; ++i)
        t[ty + i * 8][tx] = V[(size_t)(k0 + ty + i * 8) * 1024 + e0 + tx];
    __syncthreads();
#pragma unroll
    for (int i = 0; i < 4; ++i)
        Th[(size_t)(e0 + ty + i * 8) * 2048 + k0 + tx] =
            __float2half_rn(t[tx][ty + i * 8]);   // = V[k0+tx][e0+ty+i*8]
}

// ---------------- GEMM kernels ----------------
__global__ void __launch_bounds__(TPB, 1)
proj_kernel() {
    const int z = blockIdx.z;
    const int m0 = blockIdx.y * 128;
    const int n0 = blockIdx.x * 128;
    const __half* B = g_WTh + (size_t)z * 1024 * 1024;
    if (z == 0)
        gemm_core<2>(g_xh, 1024, B, 1024, m0, n0, 1024, 1.0f,
                     nullptr, g_Qh, 1024);
    else if (z == 1)
        gemm_core<2>(g_xh, 1024, B, 1024, m0, n0, 1024, 1.0f,
                     nullptr, g_Kh, 1024);
    else
        gemm_core<0>(g_xh, 1024, B, 1024, m0, n0, 1024, 1.0f,
                     g_V, nullptr, 1024);
}

__global__ void __launch_bounds__(TPB, 1)
score_kernel() {
    const int kb = blockIdx.x, qb = blockIdx.y, b = blockIdx.z;
    if (kb > qb) return;
    const size_t qo = (size_t)b * 2048 * 1024;
    gemm_core<0>(g_Qh + qo, 1024, g_Kh + qo, 1024,
                 qb * 128, kb * 128, 1024, 0.03125f,
                 g_S + (size_t)b * 2048 * 2048, nullptr, 2048);
}

__global__ void __launch_bounds__(TPB, 1)
pv_kernel(float* __restrict__ out) {
    const int nb = blockIdx.x, qb = blockIdx.y, b = blockIdx.z;
    const size_t po = (size_t)b * 2048 * 2048;
    const size_t vo = (size_t)b * 1024 * 2048;
    gemm_core<0>(g_Ph + po, 2048, g_VTh + vo, 2048,
                 qb * 128, nb * 128, (qb + 1) * 128, 1.0f,
                 out + (size_t)b * 2048 * 1024, nullptr, 1024);
}

// ---------------- softmax ----------------
__global__ void softmax_kernel() {
    const int q = blockIdx.x, b = blockIdx.y;
    float* row = g_S + ((size_t)b * 2048 + q) * 2048;
    __half* ph = g_Ph + ((size_t)b * 2048 + q) * 2048;
    const int len = q + 1;
    const int tid = threadIdx.x;
    __shared__ float red[TPB];

    float m = -1e30f;
    for (int i = tid; i < len; i += TPB) m = fmaxf(m, row[i]);
    red[tid] = m;
    __syncthreads();
#pragma unroll
    for (int s = TPB / 2; s > 0; s >>= 1) {
        if (tid < s) red[tid] = fmaxf(red[tid], red[tid + s]);
        __syncthreads();
    }
    m = red[0];
    __syncthreads();

    float sum = 0.0f;
    for (int i = tid; i < len; i += TPB) {
        float e = __expf(row[i] - m);
        row[i] = e;
        sum += e;
    }
    red[tid] = sum;
    __syncthreads();
#pragma unroll
    for (int s = TPB / 2; s > 0; s >>= 1) {
        if (tid < s) red[tid] += red[tid + s];
        __syncthreads();
    }
    const float inv = 1.0f / red[0];
    __syncthreads();

    const __half z = __float2half(0.0f);
    for (int i = tid; i < len; i += TPB)
        ph[i] = __float2half_rn(row[i] * inv);
    const int klim = ((q >> 7) + 1) << 7;  // zero up to 128-tile boundary
    for (int i = len + tid; i < klim; i += TPB) ph[i] = z;
}

// ---------------- launch ----------------
extern "C" void kernel_launch(void* const* d_in, const int* in_sizes, int n_in,
                              void* d_out, int out_size) {
    const float* x  = (const float*)d_in[0];
    const float* Wq = (const float*)d_in[1];
    const float* Wk = (const float*)d_in[2];
    const float* Wv = (const float*)d_in[3];
    float* out = (float*)d_out;

    cudaFuncSetAttribute(proj_kernel,  cudaFuncAttributeMaxDynamicSharedMemorySize, GEMM_SMEM);
    cudaFuncSetAttribute(score_kernel, cudaFuncAttributeMaxDynamicSharedMemorySize, GEMM_SMEM);
    cudaFuncSetAttribute(pv_kernel,    cudaFuncAttributeMaxDynamicSharedMemorySize, GEMM_SMEM);

    split_x_kernel<<<4096, 256>>>(x);
    wt_kernel<<<dim3(32, 32, 3), dim3(32, 8)>>>(Wq, Wk, Wv);
    proj_kernel<<<dim3(8, 64, 3), TPB, GEMM_SMEM>>>();
    vt_kernel<<<dim3(32, 64, 4), dim3(32, 8)>>>();
    score_kernel<<<dim3(16, 16, 4), TPB, GEMM_SMEM>>>();
    softmax_kernel<<<dim3(2048, 4), TPB>>>();
    pv_kernel<<<dim3(8, 16, 4), TPB, GEMM_SMEM>>>(out);
}

// round 17
// speedup vs baseline: 6.6913x; 1.0694x over previous
#include <cuda_runtime.h>
#include <cuda_fp16.h>
#include <cstdint>

// CausalAttention via pure-fp16 mma.sync (1 HMMA per k16-step).
// R17: aux-tail cuts on top of R16 (389us):
//  - V consumed via ldmatrix.x4.trans in pv_kernel -> vt_kernel + fp32 V
//    round-trip deleted (proj writes fp16 V directly).
//  - PV qb reversed so heavy causal tiles schedule first (wave balance).

typedef unsigned int u32;

#define TPB 256
#define BK 64                 // K-chunk in fp16 elems
#define LDSS 72               // padded smem row for K-major tiles (144B)
#define LDSV 136              // padded smem row for BT (V) tiles (272B)
#define TILE_B (128 * LDSS * 2)          // 18432 B per 128x64 fp16 tile
#define OFF_A 0
#define OFF_B TILE_B
#define BUF_B (2 * TILE_B)               // 36864 (BT B tile 17408 fits)
#define GEMM_SMEM (2 * BUF_B)            // double buffer = 73728 B

// ---------------- scratch (no allocation anywhere) ----------------
__device__ __half g_xh[8192 * 1024];
__device__ __half g_WTh[3 * 1024 * 1024];
__device__ __half g_Qh[4 * 2048 * 1024];
__device__ __half g_Kh[4 * 2048 * 1024];
__device__ __half g_Vh[4 * 2048 * 1024];
__device__ float  g_S[(size_t)4 * 2048 * 2048];
__device__ __half g_Ph[(size_t)4 * 2048 * 2048];

// ---------------- helpers ----------------
__device__ __forceinline__ u32 smem_u32(const void* p) {
    u32 a;
    asm("{ .reg .u64 t; cvta.to.shared.u64 t, %1; cvt.u32.u64 %0, t; }"
        : "=r"(a) : "l"(p));
    return a;
}

__device__ __forceinline__ void cp_async16(u32 dst, const void* src) {
    asm volatile("cp.async.cg.shared.global [%0], [%1], 16;"
                 :: "r"(dst), "l"(src) : "memory");
}
#define CP_COMMIT() asm volatile("cp.async.commit_group;" ::: "memory")
#define CP_WAIT(N)  asm volatile("cp.async.wait_group %0;" :: "n"(N) : "memory")

__device__ __forceinline__ void ldmx4(u32 a, u32& r0, u32& r1, u32& r2, u32& r3) {
    asm volatile("ldmatrix.sync.aligned.m8n8.x4.shared.b16 {%0,%1,%2,%3}, [%4];"
                 : "=r"(r0), "=r"(r1), "=r"(r2), "=r"(r3) : "r"(a));
}

__device__ __forceinline__ void ldmx4t(u32 a, u32& r0, u32& r1, u32& r2, u32& r3) {
    asm volatile("ldmatrix.sync.aligned.m8n8.x4.trans.shared.b16 {%0,%1,%2,%3}, [%4];"
                 : "=r"(r0), "=r"(r1), "=r"(r2), "=r"(r3) : "r"(a));
}

__device__ __forceinline__ void mma_f32(float c[4], const u32 a[4], const u32 b[2]) {
    asm volatile(
        "mma.sync.aligned.m16n8k16.row.col.f32.f16.f16.f32 "
        "{%0,%1,%2,%3}, {%4,%5,%6,%7}, {%8,%9}, {%0,%1,%2,%3};"
        : "+f"(c[0]), "+f"(c[1]), "+f"(c[2]), "+f"(c[3])
        : "r"(a[0]), "r"(a[1]), "r"(a[2]), "r"(a[3]), "r"(b[0]), "r"(b[1]));
}

// ---------------- GEMM core ----------------
// C[128x128 tile at (m0,n0)] = sum_k A[m,k]*B[n,k]; A fp16 K-major.
// BT=false: B fp16 K-major [n][k] rows (ldb = K stride).
// BT=true : B fp16 row-major [k][n] (ldb = row length) via ldmatrix.trans.
// MODE 0: fp32 out (Cf)*scale.   MODE 2: fp16 out (Ch).
template <int MODE, bool BT>
__device__ __forceinline__ void gemm_core(
    const __half* __restrict__ A, int lda,
    const __half* __restrict__ B, int ldb,
    int m0, int n0, int Klen, float scale,
    float* __restrict__ Cf, __half* __restrict__ Ch, int ldc)
{
    extern __shared__ char smem[];
    const u32 sbase = smem_u32(smem);
    const int tid = threadIdx.x;
    const int wid = tid >> 5;
    const int lane = tid & 31;
    const int warp_m = (wid & 3) * 32;   // 4 warps over M
    const int warp_n = (wid >> 2) * 64;  // 2 warps over N

    // A cp.async mapping: 32 rows x 8 segs(16B) per pass, 4 passes
    const int lrow = tid >> 3;            // 0..31
    const int lseg = (tid & 7) * 8;       // elem col 0..56
    const u32 dstA = (u32)(lrow * LDSS + lseg) * 2;
    const __half* pA = A + (size_t)(m0 + lrow) * lda + lseg;

    // B cp.async mapping
    const __half* pB;
    u32 dstB;
    int rB = 0, cB = 0;
    if (!BT) {
        pB = B + (size_t)(n0 + lrow) * ldb + lseg;
        dstB = dstA;
    } else {
        rB = tid >> 2;             // k-row 0..63
        cB = (tid & 3) * 8;        // elem col 0..24 (plus p*32)
        pB = B + (size_t)rB * ldb + n0 + cB;
        dstB = (u32)(rB * LDSV + cB) * 2;
    }

    const int nch = Klen / BK;

    // ldmatrix base offsets (within a tile)
    const u32 lm_a0 = (u32)((warp_m + (lane & 15)) * LDSS + (lane >> 4) * 8) * 2;
    const u32 lm_b0 = BT
        ? (u32)((lane & 15) * LDSV + warp_n + (lane >> 4) * 8) * 2
        : (u32)((warp_n + (lane & 15)) * LDSS + (lane >> 4) * 8) * 2;

    float acc[2][8][4];
#pragma unroll
    for (int i = 0; i < 2; ++i)
#pragma unroll
        for (int j = 0; j < 8; ++j)
#pragma unroll
            for (int q = 0; q < 4; ++q) acc[i][j][q] = 0.0f;

    // ---- prologue: load chunk 0 ----
    {
        const u32 ba = sbase;
#pragma unroll
        for (int p = 0; p < 4; ++p) {
            cp_async16(ba + OFF_A + dstA + (u32)(32 * p * LDSS) * 2,
                       pA + (size_t)(32 * p) * lda);
            if (!BT)
                cp_async16(ba + OFF_B + dstB + (u32)(32 * p * LDSS) * 2,
                           pB + (size_t)(32 * p) * ldb);
            else
                cp_async16(ba + OFF_B + dstB + (u32)(32 * p) * 2, pB + 32 * p);
        }
        CP_COMMIT();
    }

    for (int c = 0; c < nch; ++c) {
        // issue loads for chunk c+1 into the other buffer
        if (c + 1 < nch) {
            const u32 ba = sbase + ((c + 1) & 1) * BUF_B;
            const int k0 = (c + 1) * BK;
#pragma unroll
            for (int p = 0; p < 4; ++p) {
                cp_async16(ba + OFF_A + dstA + (u32)(32 * p * LDSS) * 2,
                           pA + (size_t)(32 * p) * lda + k0);
                if (!BT)
                    cp_async16(ba + OFF_B + dstB + (u32)(32 * p * LDSS) * 2,
                               pB + (size_t)(32 * p) * ldb + k0);
                else
                    cp_async16(ba + OFF_B + dstB + (u32)(32 * p) * 2,
                               pB + (size_t)k0 * ldb + 32 * p);
            }
            CP_COMMIT();
            CP_WAIT(1);   // chunk c complete, c+1 in flight
        } else {
            CP_WAIT(0);
        }
        __syncthreads();

        const u32 ba = sbase + (c & 1) * BUF_B;
        const u32 aA = ba + OFF_A + lm_a0;
        const u32 aB = ba + OFF_B + lm_b0;

#pragma unroll
        for (int ks = 0; ks < BK / 16; ++ks) {
            u32 bb[8][2];
            if (!BT) {
                const u32 ko = (u32)(ks * 16) * 2;
#pragma unroll
                for (int g = 0; g < 4; ++g) {   // 16 n-rows per ldmatrix.x4
                    u32 r0, r1, r2, r3;
                    ldmx4(aB + ko + (u32)(g * 16 * LDSS) * 2, r0, r1, r2, r3);
                    bb[2 * g][0] = r0; bb[2 * g][1] = r2;
                    bb[2 * g + 1][0] = r1; bb[2 * g + 1][1] = r3;
                }
            } else {
                const u32 ko = (u32)(ks * 16 * LDSV) * 2;
#pragma unroll
                for (int g = 0; g < 4; ++g) {   // 16 n-cols per x4.trans
                    u32 r0, r1, r2, r3;
                    ldmx4t(aB + ko + (u32)(g * 16) * 2, r0, r1, r2, r3);
                    bb[2 * g][0] = r0; bb[2 * g][1] = r1;
                    bb[2 * g + 1][0] = r2; bb[2 * g + 1][1] = r3;
                }
            }
            const u32 koA = (u32)(ks * 16) * 2;
#pragma unroll
            for (int mf = 0; mf < 2; ++mf) {
                u32 ah[4];
                ldmx4(aA + koA + (u32)(mf * 16 * LDSS) * 2,
                      ah[0], ah[1], ah[2], ah[3]);
#pragma unroll
                for (int nf = 0; nf < 8; ++nf)
                    mma_f32(acc[mf][nf], ah, bb[nf]);
            }
        }
        __syncthreads();
    }

    // ---- epilogue ----
    const int erow = lane >> 2;
    const int ecol = (lane & 3) * 2;
#pragma unroll
    for (int mf = 0; mf < 2; ++mf) {
        const int rbase = m0 + warp_m + mf * 16 + erow;
#pragma unroll
        for (int nf = 0; nf < 8; ++nf) {
            const int ccol = n0 + warp_n + nf * 8 + ecol;
            const float v0 = acc[mf][nf][0], v1 = acc[mf][nf][1];
            const float v2 = acc[mf][nf][2], v3 = acc[mf][nf][3];
            if (MODE == 0) {
                float2 w0, w1;
                w0.x = v0 * scale; w0.y = v1 * scale;
                w1.x = v2 * scale; w1.y = v3 * scale;
                *(float2*)(Cf + (size_t)rbase * ldc + ccol) = w0;
                *(float2*)(Cf + (size_t)(rbase + 8) * ldc + ccol) = w1;
            } else {
                *(__half2*)(Ch + (size_t)rbase * ldc + ccol) =
                    __halves2half2(__float2half_rn(v0), __float2half_rn(v1));
                *(__half2*)(Ch + (size_t)(rbase + 8) * ldc + ccol) =
                    __halves2half2(__float2half_rn(v2), __float2half_rn(v3));
            }
        }
    }
}

// ---------------- prep kernels ----------------
__global__ void split_x_kernel(const float* __restrict__ x) {
    const int n = 8192 * 1024;
    for (int i = blockIdx.x * blockDim.x + threadIdx.x; i < n; i += gridDim.x * blockDim.x)
        g_xh[i] = __float2half_rn(x[i]);
}

__global__ void wt_kernel(const float* __restrict__ Wq, const float* __restrict__ Wk,
                          const float* __restrict__ Wv) {
    __shared__ float t[32][33];
    const float* W = (blockIdx.z == 0) ? Wq : (blockIdx.z == 1) ? Wk : Wv;
    __half* Th = g_WTh + (size_t)blockIdx.z * 1024 * 1024;
    const int n0 = blockIdx.x * 32, k0 = blockIdx.y * 32;
    const int tx = threadIdx.x, ty = threadIdx.y;
#pragma unroll
    for (int i = 0; i < 4; ++i)
        t[ty + i * 8][tx] = W[(size_t)(k0 + ty + i * 8) * 1024 + n0 + tx];
    __syncthreads();
#pragma unroll
    for (int i = 0; i < 4; ++i)
        Th[(size_t)(n0 + ty + i * 8) * 1024 + k0 + tx] =
            __float2half_rn(t[tx][ty + i * 8]);   // = W[k0+tx][n0+ty+i*8]
}

// ---------------- GEMM kernels ----------------
__global__ void __launch_bounds__(TPB, 1)
proj_kernel() {
    const int z = blockIdx.z;
    const int m0 = blockIdx.y * 128;
    const int n0 = blockIdx.x * 128;
    const __half* B = g_WTh + (size_t)z * 1024 * 1024;
    __half* C = (z == 0) ? g_Qh : (z == 1) ? g_Kh : g_Vh;
    gemm_core<2, false>(g_xh, 1024, B, 1024, m0, n0, 1024, 1.0f,
                        nullptr, C, 1024);
}

__global__ void __launch_bounds__(TPB, 1)
score_kernel() {
    const int kb = blockIdx.x, qb = blockIdx.y, b = blockIdx.z;
    if (kb > qb) return;
    const size_t qo = (size_t)b * 2048 * 1024;
    gemm_core<0, false>(g_Qh + qo, 1024, g_Kh + qo, 1024,
                        qb * 128, kb * 128, 1024, 0.03125f,
                        g_S + (size_t)b * 2048 * 2048, nullptr, 2048);
}

__global__ void __launch_bounds__(TPB, 1)
pv_kernel(float* __restrict__ out) {
    const int nb = blockIdx.x, b = blockIdx.z;
    const int qb = gridDim.y - 1 - blockIdx.y;   // heavy tiles first
    const size_t po = (size_t)b * 2048 * 2048;
    const size_t vo = (size_t)b * 2048 * 1024;
    gemm_core<0, true>(g_Ph + po, 2048, g_Vh + vo, 1024,
                       qb * 128, nb * 128, (qb + 1) * 128, 1.0f,
                       out + (size_t)b * 2048 * 1024, nullptr, 1024);
}

// ---------------- softmax ----------------
__global__ void softmax_kernel() {
    const int q = blockIdx.x, b = blockIdx.y;
    float* row = g_S + ((size_t)b * 2048 + q) * 2048;
    __half* ph = g_Ph + ((size_t)b * 2048 + q) * 2048;
    const int len = q + 1;
    const int tid = threadIdx.x;
    __shared__ float red[TPB];

    float m = -1e30f;
    for (int i = tid; i < len; i += TPB) m = fmaxf(m, row[i]);
    red[tid] = m;
    __syncthreads();
#pragma unroll
    for (int s = TPB / 2; s > 0; s >>= 1) {
        if (tid < s) red[tid] = fmaxf(red[tid], red[tid + s]);
        __syncthreads();
    }
    m = red[0];
    __syncthreads();

    float sum = 0.0f;
    for (int i = tid; i < len; i += TPB) {
        float e = __expf(row[i] - m);
        row[i] = e;
        sum += e;
    }
    red[tid] = sum;
    __syncthreads();
#pragma unroll
    for (int s = TPB / 2; s > 0; s >>= 1) {
        if (tid < s) red[tid] += red[tid + s];
        __syncthreads();
    }
    const float inv = 1.0f / red[0];
    __syncthreads();

    const __half z = __float2half(0.0f);
    for (int i = tid; i < len; i += TPB)
        ph[i] = __float2half_rn(row[i] * inv);
    const int klim = ((q >> 7) + 1) << 7;  // zero up to 128-tile boundary
    for (int i = len + tid; i < klim; i += TPB) ph[i] = z;
}

// ---------------- launch ----------------
extern "C" void kernel_launch(void* const* d_in, const int* in_sizes, int n_in,
                              void* d_out, int out_size) {
    const float* x  = (const float*)d_in[0];
    const float* Wq = (const float*)d_in[1];
    const float* Wk = (const float*)d_in[2];
    const float* Wv = (const float*)d_in[3];
    float* out = (float*)d_out;

    cudaFuncSetAttribute(proj_kernel,  cudaFuncAttributeMaxDynamicSharedMemorySize, GEMM_SMEM);
    cudaFuncSetAttribute(score_kernel, cudaFuncAttributeMaxDynamicSharedMemorySize, GEMM_SMEM);
    cudaFuncSetAttribute(pv_kernel,    cudaFuncAttributeMaxDynamicSharedMemorySize, GEMM_SMEM);

    split_x_kernel<<<4096, 256>>>(x);
    wt_kernel<<<dim3(32, 32, 3), dim3(32, 8)>>>(Wq, Wk, Wv);
    proj_kernel<<<dim3(8, 64, 3), TPB, GEMM_SMEM>>>();
    score_kernel<<<dim3(16, 16, 4), TPB, GEMM_SMEM>>>();
    softmax_kernel<<<dim3(2048, 4), TPB>>>();
    pv_kernel<<<dim3(8, 16, 4), TPB, GEMM_SMEM>>>(out);
}